// round 11
// baseline (speedup 1.0000x reference)
#include <cuda_runtime.h>
#include <math_constants.h>

// Problem constants (fixed by setup_inputs)
#define BS     32
#define C      128
#define GN     256
#define S      16
#define NTILES 4096          // G / NG
#define NG     2             // groups per tile (consecutive gn -> memory adjacent)
#define NBLK   592           // 4/SM on 148 SMs, 4096/592 = 6.92 tiles (near-balanced)
#define NT     256
#define MAXN   9             // bg + up to 8 fg instances (labels in [-1,8))
#define INVT   5.0f          // 1 / T, T = 0.2
#define WLOSS  0.1f

// packed f32x2 helpers (sm_103a; FFMA2 only reachable via PTX)
#define FMA2(d, a, b, c) \
    asm("fma.rn.f32x2 %0, %1, %2, %3;" : "=l"(d) : "l"(a), "l"(b), "l"(c))
#define UNPK(lo, hi, v) \
    asm("mov.b64 {%0, %1}, %2;" : "=f"(lo), "=f"(hi) : "l"(v))

__device__ float2   g_part[NBLK];   // per-block (sum gl*gv, sum gv)
__device__ unsigned g_ctr = 0;      // completed-block counter (self-resetting)

__global__ __launch_bounds__(NT, 4)
void fused_kernel(const int*   __restrict__ lab_g,   // [bs, Gn, S]
                  const float* __restrict__ feat_g,  // [bs, C, Gn, S]
                  const int*   __restrict__ idx_g,   // [bs, Gn, S]
                  const float* __restrict__ ctx,     // [1, C]
                  float*       __restrict__ out)
{
    __shared__ __align__(16) float4 st4[2][C][8];       // double-buffered tile, 32KB
    __shared__ __align__(16) float  Mrow[NG][MAXN][C];  // instance means, 9KB
    __shared__ __align__(16) float  W[NG][MAXN][S];     // per-slot weights, 1.125KB
    __shared__ int    instNumB[2][NG];                  // double-buffered (phase3 vs next phase1)
    __shared__ int    hasBg[NG];
    __shared__ int    sIsLast;
    __shared__ float  red[16];

    const int t    = threadIdx.x;
    const int lane = t & 31;
    const unsigned sb0 = (unsigned)__cvta_generic_to_shared(&st4[0][0][0]);
    const int   c2   = t & 127;                 // phase-2 channel
    const int   gl2  = t >> 7;                  // phase-2 local group
    const float ctxv = __ldg(ctx + c2);

    int   tile = blockIdx.x;
    int   buf  = 0;
    float ax = 0.0f, ay = 0.0f;                 // per-warp loss accumulators
    int   pIdx = 0, pLab = 0;                   // prefetched metadata (warps 0,1)

    // ---------------- prologue: stage first tile + its metadata ----------------
    if (tile < NTILES) {
        const int g0 = tile * NG, b = g0 / GN, gn0 = g0 % GN;
        const float4* src = (const float4*)(feat_g + ((size_t)b * C * GN + gn0) * S);
        #pragma unroll
        for (int q = 0; q < 4; ++q) {
            int f4 = t + q * NT;                // 0..1023
            int c  = f4 >> 3, k = f4 & 7;
            unsigned dst = sb0 + (unsigned)((c * 8 + (k ^ (c & 7))) * 16);
            const void* gp = (const void*)(src + (size_t)c * (GN * S / 4) + k);
            asm volatile("cp.async.cg.shared.global [%0], [%1], 16;" :: "r"(dst), "l"(gp));
        }
        asm volatile("cp.async.commit_group;");
        if (t < 64 && lane < S) {
            int grp = g0 + (t >> 5);
            pIdx = idx_g[(size_t)grp * S + lane];
            pLab = lab_g[(size_t)grp * S + lane];
        }
    }

    // ---------------- persistent tile loop (double-buffered) ----------------
    for (; tile < NTILES; tile += NBLK) {
        const int  nextTile = tile + NBLK;
        const bool hasNext  = nextTile < NTILES;

        // issue prefetch of next tile into the other buffer
        if (hasNext) {
            const int g0n = nextTile * NG, bn = g0n / GN, gn0n = g0n % GN;
            const float4* src = (const float4*)(feat_g + ((size_t)bn * C * GN + gn0n) * S);
            const unsigned sb = sb0 + (unsigned)((buf ^ 1) * (C * 8 * 16));
            #pragma unroll
            for (int q = 0; q < 4; ++q) {
                int f4 = t + q * NT;
                int c  = f4 >> 3, k = f4 & 7;
                unsigned dst = sb + (unsigned)((c * 8 + (k ^ (c & 7))) * 16);
                const void* gp = (const void*)(src + (size_t)c * (GN * S / 4) + k);
                asm volatile("cp.async.cg.shared.global [%0], [%1], 16;" :: "r"(dst), "l"(gp));
            }
            asm volatile("cp.async.commit_group;");
        }

        // phase 1: warp-parallel slot metadata -> weight matrix W (warps 0,1)
        if (t < 64) {
            const int  w  = t >> 5;
            const bool sm = lane < S;
            int myIdx = sm ? pIdx : (0x40000000 | lane);   // unique sentinels on lanes >= S
            int myLab = sm ? pLab : 0;
            unsigned mi    = __match_any_sync(0xffffffffu, myIdx);
            bool     leadI = sm && (lane == (__ffs(mi) - 1));
            int      u     = __popc(__ballot_sync(0xffffffffu, leadI));  // distinct seed idx count
            bool     valid = sm && (lane < u);
            int      labm  = valid ? myLab : (0x41000000 | lane);
            unsigned ml    = __match_any_sync(0xffffffffu, labm);
            bool     isBg  = valid && (myLab < 0);
            bool     isFg  = valid && (myLab >= 0);
            int      leadLane = __ffs(ml) - 1;
            unsigned fgLead   = __ballot_sync(0xffffffffu, isFg && (lane == leadLane));
            unsigned bgB      = __ballot_sync(0xffffffffu, isBg);
            int      nfg      = __popc(fgLead);
            int   slot  = -1;
            float scale = 0.0f;
            if (valid) {
                scale = 1.0f / (float)__popc(ml);
                slot  = isBg ? 0 : (1 + __popc(fgLead & ((1u << leadLane) - 1u)));
            }
            if (sm) {
                #pragma unroll
                for (int k = 0; k < MAXN; ++k)
                    W[w][k][lane] = (slot == k) ? scale : 0.0f;   // one-hot weighted column
            }
            if (lane == 0) { instNumB[buf][w] = nfg + 1; hasBg[w] = (bgB != 0); }
            // prefetch next tile's metadata (lands during phases 2-3)
            if (hasNext && sm) {
                int grpN = nextTile * NG + w;
                pIdx = idx_g[(size_t)grpN * S + lane];
                pLab = lab_g[(size_t)grpN * S + lane];
            }
        }
        if (hasNext) asm volatile("cp.async.wait_group 1;");   // current tile resident
        else         asm volatile("cp.async.wait_group 0;");
        __syncthreads();                                       // B1

        // phase 2: per-instance means = dense 9x16 contraction in packed f32x2
        {
            unsigned long long acc2[MAXN];
            #pragma unroll
            for (int k = 0; k < MAXN; ++k) acc2[k] = 0ULL;
            const ulonglong2* stb2 = (const ulonglong2*)&st4[buf][0][0];  // [c][8] float4 view
            const ulonglong2* Wv2  = (const ulonglong2*)&W[gl2][0][0];    // W[k] = 4 x ulonglong2
            #pragma unroll
            for (int q = 0; q < 4; ++q) {
                ulonglong2 fv = stb2[c2 * 8 + ((gl2 * 4 + q) ^ (c2 & 7))];
                #pragma unroll
                for (int k = 0; k < MAXN; ++k) {
                    ulonglong2 w2 = Wv2[k * 4 + q];            // broadcast LDS.128
                    FMA2(acc2[k], fv.x, w2.x, acc2[k]);
                    FMA2(acc2[k], fv.y, w2.y, acc2[k]);
                }
            }
            #pragma unroll
            for (int k = 0; k < MAXN; ++k) {
                float lo, hi;
                UNPK(lo, hi, acc2[k]);
                Mrow[gl2][k][c2] = lo + hi;
            }
            if (!hasBg[gl2]) Mrow[gl2][0][c2] = ctxv;
        }
        __syncthreads();                                       // B2

        // phase 3: sim rows + logsumexp, half-warp per row (warp = 2 rows), f32x2 dots
        {
            const int w   = t >> 5;        // 0..7
            const int glw = w >> 2;
            const int r   = w & 3;
            const int hl  = lane >> 4;     // half index -> row select
            const int cl  = lane & 15;     // 8 channels per lane
            const int n   = instNumB[buf][glw];
            const int row = 1 + r + 4 * hl;        // 1..8
            const int fg  = n - 1;
            const ulonglong2* Mv2 = (const ulonglong2*)&Mrow[glw][0][0];  // 32 ull2 per row
            ulonglong2 a0 = Mv2[row * 32 + cl * 2];
            ulonglong2 a1 = Mv2[row * 32 + cl * 2 + 1];
            float p[MAXN];
            #pragma unroll
            for (int j = 0; j < MAXN; ++j) {
                ulonglong2 b0 = Mv2[j * 32 + cl * 2];
                ulonglong2 b1 = Mv2[j * 32 + cl * 2 + 1];
                unsigned long long pk = 0ULL;
                FMA2(pk, a0.x, b0.x, pk);
                FMA2(pk, a0.y, b0.y, pk);
                FMA2(pk, a1.x, b1.x, pk);
                FMA2(pk, a1.y, b1.y, pk);
                float lo, hi;
                UNPK(lo, hi, pk);
                p[j] = lo + hi;
            }
            #pragma unroll
            for (int o = 8; o > 0; o >>= 1) {      // 4-stage butterfly within 16-lane half
                #pragma unroll
                for (int j = 0; j < MAXN; ++j)
                    p[j] += __shfl_xor_sync(0xffffffffu, p[j], o);
            }
            float m = -CUDART_INF_F;
            #pragma unroll
            for (int j = 0; j < MAXN; ++j) {
                p[j] = (j < n) ? p[j] * INVT : -CUDART_INF_F;
                m = fmaxf(m, p[j]);
            }
            float ssum = 0.f, diag = 0.f;
            #pragma unroll
            for (int j = 0; j < MAXN; ++j) {
                ssum += __expf(p[j] - m);
                if (j == row) diag = p[j];
            }
            float li = (row < n) ? (m + __logf(ssum) - diag) : 0.0f;
            li += __shfl_xor_sync(0xffffffffu, li, 16);        // combine the 2 rows
            if (fg >= 1) {
                ax += __fdividef(li, (float)fg);               // 4 warps cover rows 1-8
                if (r == 0) ay += 1.0f;                        // group validity counted once
            }
        }
        buf ^= 1;
    }

    // ---------------- epilogue: combine 8 warp accumulators, one atomic per block ----------------
    __syncthreads();
    if (lane == 0) { red[t >> 5] = ax; red[8 + (t >> 5)] = ay; }
    __syncthreads();
    if (t == 0) {
        float sx = 0.f, sy = 0.f;
        #pragma unroll
        for (int q = 0; q < 8; ++q) { sx += red[q]; sy += red[8 + q]; }
        g_part[blockIdx.x] = make_float2(sx, sy);
        __threadfence();                          // publish before signaling
        unsigned o = atomicAdd(&g_ctr, 1u);
        sIsLast = (o == (unsigned)(NBLK - 1));
    }
    __syncthreads();

    if (sIsLast) {
        if (t == 0) __threadfence();              // acquire all g_part writes
        __syncthreads();
        float sx = 0.f, sy = 0.f;
        for (int i = t; i < NBLK; i += NT) {
            float2 v = g_part[i];
            sx += v.x; sy += v.y;
        }
        #pragma unroll
        for (int o = 16; o > 0; o >>= 1) {
            sx += __shfl_xor_sync(0xffffffffu, sx, o);
            sy += __shfl_xor_sync(0xffffffffu, sy, o);
        }
        if (lane == 0) { red[t >> 5] = sx; red[8 + (t >> 5)] = sy; }
        __syncthreads();
        if (t == 0) {
            float fx = 0.f, fy = 0.f;
            #pragma unroll
            for (int q = 0; q < 8; ++q) { fx += red[q]; fy += red[8 + q]; }
            out[0] = fx / fy * WLOSS;
            atomicExch(&g_ctr, 0u);               // visible reset for next graph replay
        }
    }
}

extern "C" void kernel_launch(void* const* d_in, const int* in_sizes, int n_in,
                              void* d_out, int out_size)
{
    const int*   lab  = (const int*)  d_in[0];   // proposal_instance_mask
    const float* feat = (const float*)d_in[1];   // grouped_features
    const int*   idx  = (const int*)  d_in[2];   // grouped_indices
    const float* ctx  = (const float*)d_in[3];   // context_compen
    (void)in_sizes; (void)n_in; (void)out_size;

    fused_kernel<<<NBLK, NT>>>(lab, feat, idx, ctx, (float*)d_out);
}

// round 14
// speedup vs baseline: 1.2721x; 1.2721x over previous
#include <cuda_runtime.h>
#include <math_constants.h>

// Problem constants (fixed by setup_inputs)
#define BS     32
#define C      128
#define GN     256
#define S      16
#define NGROUP 8192          // total groups
#define NBLK   740           // 5 blocks/SM on 148 SMs, one wave
#define NT     256
#define NSUB   (NBLK * 2)    // 1480 independent 128-thread sub-streams
#define MAXN   9             // bg + up to 8 fg instances (labels in [-1,8))
#define INVT   5.0f          // 1 / T, T = 0.2
#define WLOSS  0.1f

__device__ float2   g_part[NBLK];   // per-block (sum gl*gv, sum gv)
__device__ unsigned g_ctr = 0;      // completed-block counter (self-resetting)

__global__ __launch_bounds__(NT, 5)
void fused_kernel(const int*   __restrict__ lab_g,   // [bs, Gn, S]
                  const float* __restrict__ feat_g,  // [bs, C, Gn, S]
                  const int*   __restrict__ idx_g,   // [bs, Gn, S]
                  const float* __restrict__ ctx,     // [1, C]
                  float*       __restrict__ out)
{
    // [half][buf][channel][4 float4], swizzled pos = (k + (c>>1)) & 3 -> 32KB
    __shared__ __align__(16) float4 stA[2][2][C][4];
    __shared__ __align__(16) float  Mrow[2][MAXN][C];   // per-half instance means, 9KB
    __shared__ float2 ss2[2][S];                        // (scale, slot-as-float) per half
    __shared__ int    instNumB[2][2];                   // [buf][half] (phase3 vs next phase1)
    __shared__ int    hasBg[2];
    __shared__ int    sIsLast;
    __shared__ float  red[16];

    const int t    = threadIdx.x;
    const int half = t >> 7;            // 0,1: independent sub-stream
    const int lt   = t & 127;           // id within half
    const int lane = t & 31;
    const int wh   = lt >> 5;           // warp within half, 0..3
    const int c2   = lt;                // phase-2 channel
    const float ctxv = __ldg(ctx + c2);
    const unsigned sbase = (unsigned)__cvta_generic_to_shared(&stA[0][0][0][0])
                         + (unsigned)(half * 2) * (C * 4 * 16);

    int   g   = blockIdx.x * 2 + half;  // this sub-stream's first group
    int   buf = 0;
    float ax = 0.0f, ay = 0.0f;         // per-thread loss accumulators
    int   pIdx = 0, pLab = 0;           // prefetched metadata (warp 0 of half)

    // ---------------- prologue: stage first group + its metadata ----------------
    {
        const int b = g >> 8, gn = g & 255;
        const float4* src = (const float4*)(feat_g + ((size_t)b * C * GN + gn) * S);
        #pragma unroll
        for (int it = 0; it < 4; ++it) {
            int f4 = lt + it * 128;             // 0..511
            int c  = f4 >> 2, k = f4 & 3;
            unsigned dst = sbase + (unsigned)((c * 4 + ((k + (c >> 1)) & 3)) * 16);
            const void* gp = (const void*)(src + (size_t)c * (GN * S / 4) + k);
            asm volatile("cp.async.cg.shared.global [%0], [%1], 16;" :: "r"(dst), "l"(gp));
        }
        asm volatile("cp.async.commit_group;");
        if (wh == 0 && lane < S) {
            pIdx = idx_g[(size_t)g * S + lane];
            pLab = lab_g[(size_t)g * S + lane];
        }
    }

    // ---------------- per-half persistent group loop (double-buffered) ----------------
    for (; g < NGROUP; g += NSUB) {
        const int  gNext   = g + NSUB;
        const bool hasNext = gNext < NGROUP;

        // issue prefetch of next group into the other buffer
        if (hasNext) {
            const int bn = gNext >> 8, gnn = gNext & 255;
            const float4* src = (const float4*)(feat_g + ((size_t)bn * C * GN + gnn) * S);
            const unsigned sb = sbase + (unsigned)(buf ^ 1) * (C * 4 * 16);
            #pragma unroll
            for (int it = 0; it < 4; ++it) {
                int f4 = lt + it * 128;
                int c  = f4 >> 2, k = f4 & 3;
                unsigned dst = sb + (unsigned)((c * 4 + ((k + (c >> 1)) & 3)) * 16);
                const void* gp = (const void*)(src + (size_t)c * (GN * S / 4) + k);
                asm volatile("cp.async.cg.shared.global [%0], [%1], 16;" :: "r"(dst), "l"(gp));
            }
            asm volatile("cp.async.commit_group;");
        }

        // phase 1: warp-parallel slot metadata (warp 0 of half)
        if (wh == 0) {
            const bool sm = lane < S;
            int myIdx = sm ? pIdx : (0x40000000 | lane);   // unique sentinels on lanes >= S
            int myLab = sm ? pLab : 0;
            unsigned mi    = __match_any_sync(0xffffffffu, myIdx);
            bool     leadI = sm && (lane == (__ffs(mi) - 1));
            int      u     = __popc(__ballot_sync(0xffffffffu, leadI));  // distinct seed idx count
            bool     valid = sm && (lane < u);
            int      labm  = valid ? myLab : (0x41000000 | lane);
            unsigned ml    = __match_any_sync(0xffffffffu, labm);
            bool     isBg  = valid && (myLab < 0);
            bool     isFg  = valid && (myLab >= 0);
            int      leadLane = __ffs(ml) - 1;
            unsigned fgLead   = __ballot_sync(0xffffffffu, isFg && (lane == leadLane));
            unsigned bgB      = __ballot_sync(0xffffffffu, isBg);
            int      nfg      = __popc(fgLead);
            int   slot  = -1;
            float scale = 0.0f;
            if (valid) {
                scale = 1.0f / (float)__popc(ml);
                slot  = isBg ? 0 : (1 + __popc(fgLead & ((1u << leadLane) - 1u)));
            }
            if (sm) ss2[half][lane] = make_float2(scale, __int_as_float(slot));
            if (lane == 0) { instNumB[buf][half] = nfg + 1; hasBg[half] = (bgB != 0); }
            // prefetch next group's metadata (lands during phases 2-3)
            if (hasNext && sm) {
                pIdx = idx_g[(size_t)gNext * S + lane];
                pLab = lab_g[(size_t)gNext * S + lane];
            }
        }
        if (hasNext) asm volatile("cp.async.wait_group 1;");   // current tile resident
        else         asm volatile("cp.async.wait_group 0;");
        asm volatile("bar.sync %0, 128;" :: "r"(1 + half) : "memory");   // B1 (per-half)

        // phase 2: per-instance means, register accumulators (all 128 threads of half)
        {
            float acc[MAXN];
            #pragma unroll
            for (int k = 0; k < MAXN; ++k) acc[k] = 0.0f;
            const float4 (*stb)[4] = stA[half][buf];
            #pragma unroll
            for (int q = 0; q < 4; ++q) {
                float4 fv = stb[c2][(q + (c2 >> 1)) & 3];
                float fq[4] = {fv.x, fv.y, fv.z, fv.w};
                #pragma unroll
                for (int u4 = 0; u4 < 4; ++u4) {
                    float2 sv = ss2[half][q * 4 + u4];
                    int    sl = __float_as_int(sv.y);
                    float  v  = fq[u4] * sv.x;
                    #pragma unroll
                    for (int k = 0; k < MAXN; ++k)
                        if (sl == k) acc[k] += v;      // independent predicated adds
                }
            }
            #pragma unroll
            for (int k = 0; k < MAXN; ++k) Mrow[half][k][c2] = acc[k];
            if (!hasBg[half]) Mrow[half][0][c2] = ctxv;
        }
        asm volatile("bar.sync %0, 128;" :: "r"(1 + half) : "memory");   // B2 (per-half)

        // phase 3: sim rows + logsumexp, half-warp per row (warp = 2 rows)
        {
            const int hl  = lane >> 4;     // half-warp index -> row select
            const int cl  = lane & 15;     // 8 channels per lane
            const int n   = instNumB[buf][half];
            const int row = 1 + wh + 4 * hl;       // 1..8
            const int fg  = n - 1;
            const float4* Mv = (const float4*)&Mrow[half][0][0];   // 32 float4 per row
            float4 a0 = Mv[row * 32 + cl * 2];
            float4 a1 = Mv[row * 32 + cl * 2 + 1];
            float p[MAXN];
            #pragma unroll
            for (int j = 0; j < MAXN; ++j) {
                float4 b0 = Mv[j * 32 + cl * 2];
                float4 b1 = Mv[j * 32 + cl * 2 + 1];
                p[j] = a0.x*b0.x + a0.y*b0.y + a0.z*b0.z + a0.w*b0.w
                     + a1.x*b1.x + a1.y*b1.y + a1.z*b1.z + a1.w*b1.w;
            }
            #pragma unroll
            for (int o = 8; o > 0; o >>= 1) {      // 4-stage butterfly within 16-lane half
                #pragma unroll
                for (int j = 0; j < MAXN; ++j)
                    p[j] += __shfl_xor_sync(0xffffffffu, p[j], o);
            }
            float m = -CUDART_INF_F;
            #pragma unroll
            for (int j = 0; j < MAXN; ++j) {
                p[j] = (j < n) ? p[j] * INVT : -CUDART_INF_F;
                m = fmaxf(m, p[j]);
            }
            float ssum = 0.f, diag = 0.f;
            #pragma unroll
            for (int j = 0; j < MAXN; ++j) {
                ssum += __expf(p[j] - m);
                if (j == row) diag = p[j];
            }
            float li = (row < n) ? (m + __logf(ssum) - diag) : 0.0f;
            li += __shfl_xor_sync(0xffffffffu, li, 16);        // combine the warp's 2 rows
            if (fg >= 1) {
                ax += __fdividef(li, (float)fg);               // 4 warps cover rows 1-8
                if (wh == 0) ay += 1.0f;                       // group validity counted once
            }
        }
        buf ^= 1;
    }

    // ---------------- epilogue: combine 8 warp accumulators, one atomic per block ----------------
    __syncthreads();
    if (lane == 0) { red[t >> 5] = ax; red[8 + (t >> 5)] = ay; }
    __syncthreads();
    if (t == 0) {
        float sx = 0.f, sy = 0.f;
        #pragma unroll
        for (int q = 0; q < 8; ++q) { sx += red[q]; sy += red[8 + q]; }
        g_part[blockIdx.x] = make_float2(sx, sy);
        __threadfence();                          // publish before signaling
        unsigned o = atomicAdd(&g_ctr, 1u);
        sIsLast = (o == (unsigned)(NBLK - 1));
    }
    __syncthreads();

    if (sIsLast) {
        if (t == 0) __threadfence();              // acquire all g_part writes
        __syncthreads();
        float sx = 0.f, sy = 0.f;
        for (int i = t; i < NBLK; i += NT) {
            float2 v = g_part[i];
            sx += v.x; sy += v.y;
        }
        #pragma unroll
        for (int o = 16; o > 0; o >>= 1) {
            sx += __shfl_xor_sync(0xffffffffu, sx, o);
            sy += __shfl_xor_sync(0xffffffffu, sy, o);
        }
        if (lane == 0) { red[t >> 5] = sx; red[8 + (t >> 5)] = sy; }
        __syncthreads();
        if (t == 0) {
            float fx = 0.f, fy = 0.f;
            #pragma unroll
            for (int q = 0; q < 8; ++q) { fx += red[q]; fy += red[8 + q]; }
            out[0] = fx / fy * WLOSS;
            atomicExch(&g_ctr, 0u);               // visible reset for next graph replay
        }
    }
}

extern "C" void kernel_launch(void* const* d_in, const int* in_sizes, int n_in,
                              void* d_out, int out_size)
{
    const int*   lab  = (const int*)  d_in[0];   // proposal_instance_mask
    const float* feat = (const float*)d_in[1];   // grouped_features
    const int*   idx  = (const int*)  d_in[2];   // grouped_indices
    const float* ctx  = (const float*)d_in[3];   // context_compen
    (void)in_sizes; (void)n_in; (void)out_size;

    fused_kernel<<<NBLK, NT>>>(lab, feat, idx, ctx, (float*)d_out);
}

// round 15
// speedup vs baseline: 1.5341x; 1.2060x over previous
#include <cuda_runtime.h>
#include <math_constants.h>

// Problem constants (fixed by setup_inputs)
#define BS    32
#define C     128
#define GN    256
#define S     16
#define NG    2              // groups per block (consecutive gn -> memory adjacent)
#define NB    4096           // G / NG
#define NT    256
#define MAXN  9              // bg + up to 8 fg instances (labels in [-1,8))
#define INVT  5.0f           // 1 / T, T = 0.2
#define WLOSS 0.1f

__device__ float2   g_part[NB];    // per-block (sum gl*gv, sum gv)
__device__ unsigned g_ctr = 0;     // completed-block counter (self-resetting)

__global__ __launch_bounds__(NT, 6)
void fused_kernel(const int*   __restrict__ lab_g,   // [bs, Gn, S]
                  const float* __restrict__ feat_g,  // [bs, C, Gn, S]
                  const int*   __restrict__ idx_g,   // [bs, Gn, S]
                  const float* __restrict__ ctx,     // [1, C]
                  float*       __restrict__ out)
{
    __shared__ __align__(16) float4 st4[C][8];          // tile, XOR-swizzled, 16KB
    __shared__ __align__(16) float  Mrow[NG][MAXN][C];  // instance means, 9KB
    __shared__ __align__(16) float  W[NG][MAXN][S];     // per-slot weight rows, 1.125KB
    __shared__ int    instNum[NG];
    __shared__ int    hasBg[NG];
    __shared__ int    sIsLast;
    __shared__ float  red[16];

    const int t    = threadIdx.x;
    const int lane = t & 31;
    const int g0   = blockIdx.x * NG;
    const int b    = g0 / GN;
    const int gn0  = g0 % GN;
    const int c2   = t & 127;                 // phase-2 channel
    const int gl2  = t >> 7;                  // phase-2 local group

    // ---------------- Phase 0: async coalesced gmem -> smem staging ----------------
    {
        const float4* src = (const float4*)(feat_g + ((size_t)b * C * GN + gn0) * S);
        unsigned sbase = (unsigned)__cvta_generic_to_shared(&st4[0][0]);
        #pragma unroll
        for (int q = 0; q < 4; ++q) {
            int f4 = t + q * NT;              // 0..1023
            int c  = f4 >> 3, k = f4 & 7;
            unsigned dst = sbase + (unsigned)((c * 8 + (k ^ (c & 7))) * 16);
            const void* gp = (const void*)(src + (size_t)c * (GN * S / 4) + k);
            asm volatile("cp.async.cg.shared.global [%0], [%1], 16;" :: "r"(dst), "l"(gp));
        }
        asm volatile("cp.async.commit_group;");
    }

    // ---------------- Phase 1: warp-parallel slot metadata -> W (warps 0,1) ----------------
    if (t < 64) {
        const int  w    = t >> 5;             // local group
        const bool sm   = lane < S;
        const int  grp  = g0 + w;
        int myIdx = sm ? idx_g[(size_t)grp * S + lane] : (0x40000000 | lane);
        int myLab = sm ? lab_g[(size_t)grp * S + lane] : 0;
        unsigned mi    = __match_any_sync(0xffffffffu, myIdx);
        bool     leadI = sm && (lane == (__ffs(mi) - 1));
        int      u     = __popc(__ballot_sync(0xffffffffu, leadI));   // distinct seed idx count
        bool     valid = sm && (lane < u);
        int      labm  = valid ? myLab : (0x41000000 | lane);
        unsigned ml    = __match_any_sync(0xffffffffu, labm);
        bool     isBg  = valid && (myLab < 0);
        bool     isFg  = valid && (myLab >= 0);
        int      leadLane = __ffs(ml) - 1;
        unsigned fgLead   = __ballot_sync(0xffffffffu, isFg && (lane == leadLane));
        unsigned bgB      = __ballot_sync(0xffffffffu, isBg);
        int      nfg      = __popc(fgLead);
        int   slot  = -1;
        float scale = 0.0f;
        if (valid) {
            scale = 1.0f / (float)__popc(ml);
            slot  = isBg ? 0 : (1 + __popc(fgLead & ((1u << leadLane) - 1u)));
        }
        if (sm) {
            #pragma unroll
            for (int k = 0; k < MAXN; ++k)
                W[w][k][lane] = (slot == k) ? scale : 0.0f;   // one-hot weighted columns
        }
        if (lane == 0) { instNum[w] = nfg + 1; hasBg[w] = (bgB != 0); }
    }
    asm volatile("cp.async.wait_group 0;");
    __syncthreads();                                           // B1

    // ---------------- Phase 2: per-instance means = dense 9x16 contraction ----------------
    {
        float acc[MAXN];
        #pragma unroll
        for (int k = 0; k < MAXN; ++k) acc[k] = 0.0f;
        const float4* Wv = (const float4*)&W[gl2][0][0];       // W[k] = 4 float4 (uniform addr)
        #pragma unroll
        for (int q = 0; q < 4; ++q) {
            float4 fv = st4[c2][(gl2 * 4 + q) ^ (c2 & 7)];
            #pragma unroll
            for (int k = 0; k < MAXN; ++k) {
                float4 wq = Wv[k * 4 + q];                     // broadcast LDS.128
                acc[k] += fv.x * wq.x + fv.y * wq.y + fv.z * wq.z + fv.w * wq.w;
            }
        }
        #pragma unroll
        for (int k = 0; k < MAXN; ++k) Mrow[gl2][k][c2] = acc[k];
        if (!hasBg[gl2]) Mrow[gl2][0][c2] = __ldg(ctx + c2);   // ctx replaces missing bg
    }
    __syncthreads();                                           // B2

    // ---------------- Phase 3: sim rows + logsumexp, half-warp per row ----------------
    float ax = 0.0f, ay = 0.0f;
    {
        const int w   = t >> 5;        // 0..7
        const int glw = w >> 2;
        const int r   = w & 3;
        const int hl  = lane >> 4;     // half-warp -> row select
        const int cl  = lane & 15;     // 8 channels per lane
        const int n   = instNum[glw];
        const int row = 1 + r + 4 * hl;        // 1..8
        const int fg  = n - 1;
        const float4* Mv = (const float4*)&Mrow[glw][0][0];    // 32 float4 per row
        float4 a0 = Mv[row * 32 + cl * 2];
        float4 a1 = Mv[row * 32 + cl * 2 + 1];
        float p[MAXN];
        #pragma unroll
        for (int j = 0; j < MAXN; ++j) {
            float4 b0 = Mv[j * 32 + cl * 2];                   // rows >= n are zero: safe
            float4 b1 = Mv[j * 32 + cl * 2 + 1];
            p[j] = a0.x*b0.x + a0.y*b0.y + a0.z*b0.z + a0.w*b0.w
                 + a1.x*b1.x + a1.y*b1.y + a1.z*b1.z + a1.w*b1.w;
        }
        #pragma unroll
        for (int o = 8; o > 0; o >>= 1) {      // 4-stage butterfly within 16-lane half
            #pragma unroll
            for (int j = 0; j < MAXN; ++j)
                p[j] += __shfl_xor_sync(0xffffffffu, p[j], o);
        }
        float m = -CUDART_INF_F;
        #pragma unroll
        for (int j = 0; j < MAXN; ++j) {
            p[j] = (j < n) ? p[j] * INVT : -CUDART_INF_F;
            m = fmaxf(m, p[j]);
        }
        float ssum = 0.f, diag = 0.f;
        #pragma unroll
        for (int j = 0; j < MAXN; ++j) {
            ssum += __expf(p[j] - m);
            if (j == row) diag = p[j];
        }
        float li = (row < n) ? (m + __logf(ssum) - diag) : 0.0f;
        li += __shfl_xor_sync(0xffffffffu, li, 16);            // combine the warp's 2 rows
        if (fg >= 1) {
            ax = __fdividef(li, (float)fg);                    // 4 warps cover rows 1-8
            ay = (r == 0) ? 1.0f : 0.0f;                       // count group once
        }
    }
    __syncthreads();                                           // B3
    if (lane == 0) { red[t >> 5] = ax; red[8 + (t >> 5)] = ay; }
    __syncthreads();

    // ---------------- Phase 4: per-block partial + completion signal ----------------
    if (t == 0) {
        float sx = 0.f, sy = 0.f;
        #pragma unroll
        for (int q = 0; q < 8; ++q) { sx += red[q]; sy += red[8 + q]; }
        g_part[blockIdx.x] = make_float2(sx, sy);
        __threadfence();                          // publish before signaling
        unsigned o = atomicAdd(&g_ctr, 1u);
        sIsLast = (o == (unsigned)(NB - 1));
    }
    __syncthreads();

    // ---------------- Phase 5: last block performs the deterministic final reduce ----------------
    if (sIsLast) {
        if (t == 0) __threadfence();              // acquire all g_part writes
        __syncthreads();
        const float4* gp = (const float4*)g_part; // NB/2 float4
        float sx = 0.f, sy = 0.f;
        #pragma unroll 4
        for (int i = t; i < NB / 2; i += NT) {
            float4 v = gp[i];
            sx += v.x + v.z;
            sy += v.y + v.w;
        }
        #pragma unroll
        for (int o = 16; o > 0; o >>= 1) {
            sx += __shfl_xor_sync(0xffffffffu, sx, o);
            sy += __shfl_xor_sync(0xffffffffu, sy, o);
        }
        if (lane == 0) { red[t >> 5] = sx; red[8 + (t >> 5)] = sy; }
        __syncthreads();
        if (t == 0) {
            float fx = 0.f, fy = 0.f;
            #pragma unroll
            for (int q = 0; q < 8; ++q) { fx += red[q]; fy += red[8 + q]; }
            out[0] = fx / fy * WLOSS;
            atomicExch(&g_ctr, 0u);               // visible reset for next graph replay
        }
    }
}

extern "C" void kernel_launch(void* const* d_in, const int* in_sizes, int n_in,
                              void* d_out, int out_size)
{
    const int*   lab  = (const int*)  d_in[0];   // proposal_instance_mask
    const float* feat = (const float*)d_in[1];   // grouped_features
    const int*   idx  = (const int*)  d_in[2];   // grouped_indices
    const float* ctx  = (const float*)d_in[3];   // context_compen
    (void)in_sizes; (void)n_in; (void)out_size;

    fused_kernel<<<NB, NT>>>(lab, feat, idx, ctx, (float*)d_out);
}

// round 16
// speedup vs baseline: 2.1780x; 1.4197x over previous
#include <cuda_runtime.h>
#include <math_constants.h>

// Problem constants (fixed by setup_inputs)
#define BS    32
#define C     128
#define GN    256
#define S     16
#define NG    4              // groups per block (consecutive gn -> memory adjacent)
#define NB    2048           // 8192 / NG
#define NT    256
#define GS4   1024           // GN*S/4, float4 channel stride
#define MAXN  9              // bg + up to 8 fg instances (labels in [-1,8))
#define INVT  5.0f           // 1 / T, T = 0.2
#define WLOSS 0.1f

__device__ float2   g_part[NB];    // per-block (sum gl*gv, sum gv)
__device__ unsigned g_ctr = 0;     // completed-block counter (self-resetting)

__global__ __launch_bounds__(NT, 4)
void fused_kernel(const int*   __restrict__ lab_g,   // [bs, Gn, S]
                  const float* __restrict__ feat_g,  // [bs, C, Gn, S]
                  const int*   __restrict__ idx_g,   // [bs, Gn, S]
                  const float* __restrict__ ctx,     // [1, C]
                  float*       __restrict__ out)
{
    __shared__ __align__(16) float4 st4[C][16];         // 4-group tile, swizzled, 32KB
    __shared__ __align__(16) float  Mrow[NG][MAXN][C];  // instance means, 18KB
    __shared__ __align__(16) float  W[NG][MAXN][S];     // per-slot weight rows, 2.25KB
    __shared__ int    instNum[NG];
    __shared__ int    hasBg[NG];
    __shared__ int    sIsLast;
    __shared__ float  red[16];

    const int t    = threadIdx.x;
    const int lane = t & 31;
    const int g0   = blockIdx.x * NG;
    const int b    = g0 / GN;
    const int gn0  = g0 % GN;                  // NG=4 divides GN -> no b crossing
    const int gl2  = t >> 6;                   // phase-2 local group (0..3)
    const int ch0  = t & 63;                   // phase-2 channel pair: ch0, ch0+64
    const int ch1  = ch0 + 64;
    const float ctxv0 = __ldg(ctx + ch0);
    const float ctxv1 = __ldg(ctx + ch1);

    // ---------------- Phase 0: async coalesced gmem -> smem staging (4 groups) ----------------
    {
        const float4* src = (const float4*)(feat_g + ((size_t)b * C * GN + gn0) * S);
        unsigned sbase = (unsigned)__cvta_generic_to_shared(&st4[0][0]);
        #pragma unroll
        for (int q = 0; q < 8; ++q) {
            int f4 = t + q * NT;               // 0..2047
            int c  = f4 >> 4, k = f4 & 15;
            unsigned dst = sbase + (unsigned)((c * 16 + (k ^ (c & 15))) * 16);
            const void* gp = (const void*)(src + (size_t)c * GS4 + k);
            asm volatile("cp.async.cg.shared.global [%0], [%1], 16;" :: "r"(dst), "l"(gp));
        }
        asm volatile("cp.async.commit_group;");
    }

    // ---------------- Phase 1: warp-parallel slot metadata -> W (warps 0-3) ----------------
    if (t < 128) {
        const int  w    = t >> 5;              // local group 0..3
        const bool sm   = lane < S;
        const int  grp  = g0 + w;
        int myIdx = sm ? idx_g[(size_t)grp * S + lane] : (0x40000000 | lane);
        int myLab = sm ? lab_g[(size_t)grp * S + lane] : 0;
        unsigned mi    = __match_any_sync(0xffffffffu, myIdx);
        bool     leadI = sm && (lane == (__ffs(mi) - 1));
        int      u     = __popc(__ballot_sync(0xffffffffu, leadI));   // distinct seed idx count
        bool     valid = sm && (lane < u);
        int      labm  = valid ? myLab : (0x41000000 | lane);
        unsigned ml    = __match_any_sync(0xffffffffu, labm);
        bool     isBg  = valid && (myLab < 0);
        bool     isFg  = valid && (myLab >= 0);
        int      leadLane = __ffs(ml) - 1;
        unsigned fgLead   = __ballot_sync(0xffffffffu, isFg && (lane == leadLane));
        unsigned bgB      = __ballot_sync(0xffffffffu, isBg);
        int      nfg      = __popc(fgLead);
        int   slot  = -1;
        float scale = 0.0f;
        if (valid) {
            scale = 1.0f / (float)__popc(ml);
            slot  = isBg ? 0 : (1 + __popc(fgLead & ((1u << leadLane) - 1u)));
        }
        if (sm) {
            #pragma unroll
            for (int k = 0; k < MAXN; ++k)
                W[w][k][lane] = (slot == k) ? scale : 0.0f;   // one-hot weighted columns
        }
        if (lane == 0) { instNum[w] = nfg + 1; hasBg[w] = (bgB != 0); }
    }
    asm volatile("cp.async.wait_group 0;");
    __syncthreads();                                           // B1

    // ---------------- Phase 2: means = dense 9x16 contraction, 2 channels/thread ----------------
    {
        float acc0[MAXN], acc1[MAXN];
        #pragma unroll
        for (int k = 0; k < MAXN; ++k) { acc0[k] = 0.0f; acc1[k] = 0.0f; }
        const float4* Wv = (const float4*)&W[gl2][0][0];       // W[k] = 4 float4 (uniform addr)
        #pragma unroll
        for (int q = 0; q < 4; ++q) {
            float4 f0 = st4[ch0][(gl2 * 4 + q) ^ (ch0 & 15)];
            float4 f1 = st4[ch1][(gl2 * 4 + q) ^ (ch1 & 15)];
            #pragma unroll
            for (int k = 0; k < MAXN; ++k) {
                float4 wq = Wv[k * 4 + q];                     // broadcast, amortized over 2 ch
                acc0[k] += f0.x * wq.x + f0.y * wq.y + f0.z * wq.z + f0.w * wq.w;
                acc1[k] += f1.x * wq.x + f1.y * wq.y + f1.z * wq.z + f1.w * wq.w;
            }
        }
        #pragma unroll
        for (int k = 0; k < MAXN; ++k) {
            Mrow[gl2][k][ch0] = acc0[k];
            Mrow[gl2][k][ch1] = acc1[k];
        }
        if (!hasBg[gl2]) { Mrow[gl2][0][ch0] = ctxv0; Mrow[gl2][0][ch1] = ctxv1; }
    }
    __syncthreads();                                           // B2

    // ---------------- Phase 3: sim + logsumexp, half-warp = 2 rows of one group ----------------
    float ax = 0.0f, ay = 0.0f;
    {
        const int w   = t >> 5;            // 0..7
        const int grp = w >> 1;            // 2 warps per group
        const int h   = lane >> 4;
        const int rp  = (w & 1) * 2 + h;   // 0..3
        const int cl  = lane & 15;
        const int n   = instNum[grp];
        const int fg  = n - 1;
        const int r1  = 1 + rp;            // 1..4
        const int r2  = 5 + rp;            // 5..8
        const float4* Mv = (const float4*)&Mrow[grp][0][0];    // 32 float4 per row
        float4 a10 = Mv[r1 * 32 + cl], a11 = Mv[r1 * 32 + cl + 16];
        float4 a20 = Mv[r2 * 32 + cl], a21 = Mv[r2 * 32 + cl + 16];
        float p1[MAXN], p2[MAXN];
        #pragma unroll
        for (int j = 0; j < MAXN; ++j) {
            float4 b0 = Mv[j * 32 + cl];                       // shared by both rows
            float4 b1 = Mv[j * 32 + cl + 16];
            p1[j] = a10.x*b0.x + a10.y*b0.y + a10.z*b0.z + a10.w*b0.w
                  + a11.x*b1.x + a11.y*b1.y + a11.z*b1.z + a11.w*b1.w;
            p2[j] = a20.x*b0.x + a20.y*b0.y + a20.z*b0.z + a20.w*b0.w
                  + a21.x*b1.x + a21.y*b1.y + a21.z*b1.z + a21.w*b1.w;
        }
        #pragma unroll
        for (int o = 8; o > 0; o >>= 1) {      // 4-stage butterfly, 18 independent chains
            #pragma unroll
            for (int j = 0; j < MAXN; ++j) {
                p1[j] += __shfl_xor_sync(0xffffffffu, p1[j], o);
                p2[j] += __shfl_xor_sync(0xffffffffu, p2[j], o);
            }
        }
        float m1 = -CUDART_INF_F, m2 = -CUDART_INF_F;
        #pragma unroll
        for (int j = 0; j < MAXN; ++j) {
            p1[j] = (j < n) ? p1[j] * INVT : -CUDART_INF_F;
            p2[j] = (j < n) ? p2[j] * INVT : -CUDART_INF_F;
            m1 = fmaxf(m1, p1[j]);
            m2 = fmaxf(m2, p2[j]);
        }
        float s1 = 0.f, s2 = 0.f, d1 = 0.f, d2 = 0.f;
        #pragma unroll
        for (int j = 0; j < MAXN; ++j) {
            s1 += __expf(p1[j] - m1);
            s2 += __expf(p2[j] - m2);
            if (j == r1) d1 = p1[j];
            if (j == r2) d2 = p2[j];
        }
        float li = 0.0f;
        if (r1 < n) li += m1 + __logf(s1) - d1;
        if (r2 < n) li += m2 + __logf(s2) - d2;
        li += __shfl_xor_sync(0xffffffffu, li, 16);            // combine the warp's 4 rows
        if (fg >= 1) {
            ax = __fdividef(li, (float)fg);                    // 2 warps cover the 8 rows
            ay = ((w & 1) == 0) ? 1.0f : 0.0f;                 // count group once
        }
    }
    __syncthreads();                                           // B3
    if (lane == 0) { red[t >> 5] = ax; red[8 + (t >> 5)] = ay; }
    __syncthreads();

    // ---------------- Phase 4: per-block partial + completion signal ----------------
    if (t == 0) {
        float sx = 0.f, sy = 0.f;
        #pragma unroll
        for (int q = 0; q < 8; ++q) { sx += red[q]; sy += red[8 + q]; }
        g_part[blockIdx.x] = make_float2(sx, sy);
        __threadfence();                          // publish before signaling
        unsigned o = atomicAdd(&g_ctr, 1u);
        sIsLast = (o == (unsigned)(NB - 1));
    }
    __syncthreads();

    // ---------------- Phase 5: last block performs the deterministic final reduce ----------------
    if (sIsLast) {
        if (t == 0) __threadfence();              // acquire all g_part writes
        __syncthreads();
        const float4* gp = (const float4*)g_part; // NB/2 float4
        float sx = 0.f, sy = 0.f;
        #pragma unroll 4
        for (int i = t; i < NB / 2; i += NT) {
            float4 v = gp[i];
            sx += v.x + v.z;
            sy += v.y + v.w;
        }
        #pragma unroll
        for (int o = 16; o > 0; o >>= 1) {
            sx += __shfl_xor_sync(0xffffffffu, sx, o);
            sy += __shfl_xor_sync(0xffffffffu, sy, o);
        }
        if (lane == 0) { red[t >> 5] = sx; red[8 + (t >> 5)] = sy; }
        __syncthreads();
        if (t == 0) {
            float fx = 0.f, fy = 0.f;
            #pragma unroll
            for (int q = 0; q < 8; ++q) { fx += red[q]; fy += red[8 + q]; }
            out[0] = fx / fy * WLOSS;
            atomicExch(&g_ctr, 0u);               // visible reset for next graph replay
        }
    }
}

extern "C" void kernel_launch(void* const* d_in, const int* in_sizes, int n_in,
                              void* d_out, int out_size)
{
    const int*   lab  = (const int*)  d_in[0];   // proposal_instance_mask
    const float* feat = (const float*)d_in[1];   // grouped_features
    const int*   idx  = (const int*)  d_in[2];   // grouped_indices
    const float* ctx  = (const float*)d_in[3];   // context_compen
    (void)in_sizes; (void)n_in; (void)out_size;

    fused_kernel<<<NB, NT>>>(lab, feat, idx, ctx, (float*)d_out);
}